// round 11
// baseline (speedup 1.0000x reference)
#include <cuda_runtime.h>

// ChamferLoss: B=8, N=M=8192, D=3 fp32, inputs ~ N(0,1).
// out = mean_n min_m ||gt_n - pred_m||^2 + mean_m min_n ||pred_m - gt_n||^2
//
// R10: algorithmic pivot. Brute force converged at ~150us (structural
// per-instruction cost, invariant to occupancy/scheduling/pipe mix).
// Replace O(N*M) with exact grid-accelerated nearest neighbor:
//   1. counting-sort both point clouds into a 32^3 uniform grid (per batch,
//      per side), points stored as float4 with original index in .w
//   2. each query point (processed in grid-sorted order for warp coherence)
//      scans expanding Chebyshev shells of the OTHER side's grid; after
//      finishing shell r, any unscanned point is >= r*h away, so stop when
//      best_d2 <= (r*h)^2  -> exact minimum.
//   3. per-point mins written to ORIGINAL indices -> fixed-order tree sum
//      -> bitwise deterministic despite atomic scatter.
// Expected candidate evaluations ~34M vs 1.07G brute force.

#define BATCH   8
#define NPTS    8192
#define G       32
#define CELLS   (G * G * G)
#define NSB     (2 * BATCH)            // (side,batch) slots; side 0=gts 1=preds
#define RANGE   6.0f                   // grid covers [-6,6]^3; max|coord|~4.7
#define HCELL   (2.0f * RANGE / G)     // 0.375
#define INVH    ((float)G / (2.0f * RANGE))
#define NTOT    (NSB * NPTS)           // 131072 points total
#define FINF    3.402823466e+38f

__device__ int    g_count [NSB * CELLS];        // per-cell point counts
__device__ int    g_cursor[NSB * CELLS];        // scatter cursors
__device__ int    g_offs  [NSB * (CELLS + 1)];  // exclusive prefix sums
__device__ float4 g_sorted[NSB * NPTS];         // cell-sorted points, .w=orig idx
__device__ float  g_minbuf[NSB * NPTS];         // per-point min d2, by orig idx
__device__ float  g_blocksums[512];

__device__ __forceinline__ int cell_of(float x, float y, float z,
                                       int& cx, int& cy, int& cz) {
    cx = min(G - 1, max(0, (int)floorf((x + RANGE) * INVH)));
    cy = min(G - 1, max(0, (int)floorf((y + RANGE) * INVH)));
    cz = min(G - 1, max(0, (int)floorf((z + RANGE) * INVH)));
    return (cz * G + cy) * G + cx;
}

// 1. zero counts + cursors (re-done every launch: graph replays must rebuild)
__global__ __launch_bounds__(256)
void k_zero() {
    int i = blockIdx.x * 256 + threadIdx.x;
    int n = NSB * CELLS;
    for (; i < 2 * n; i += gridDim.x * 256) {
        if (i < n) g_count[i] = 0;
        else       g_cursor[i - n] = 0;
    }
}

// 2. count points per cell
__global__ __launch_bounds__(256)
void k_count(const float* __restrict__ gts, const float* __restrict__ preds) {
    int idx = blockIdx.x * 256 + threadIdx.x;          // 0..NTOT-1
    int sb  = idx / NPTS;                              // side*8+batch
    int i   = idx - sb * NPTS;
    int side = sb >> 3, b = sb & 7;
    const float* p = (side == 0 ? gts : preds) + ((size_t)b * NPTS + i) * 3;
    int cx, cy, cz;
    int c = cell_of(p[0], p[1], p[2], cx, cy, cz);
    atomicAdd(&g_count[sb * CELLS + c], 1);
}

// 3. exclusive prefix sum per (side,batch): 16 blocks x 1024 threads,
//    each thread owns 32 consecutive cells.
__global__ __launch_bounds__(1024)
void k_scan() {
    const int sb = blockIdx.x;
    const int t  = threadIdx.x;
    const int base = sb * CELLS + t * 32;

    int s = 0;
#pragma unroll
    for (int k = 0; k < 32; ++k) s += g_count[base + k];

    // block inclusive scan of the 1024 thread sums
    __shared__ int ws[32];
    int lane = t & 31, wid = t >> 5;
    int v = s;
#pragma unroll
    for (int d = 1; d < 32; d <<= 1) {
        int n = __shfl_up_sync(0xFFFFFFFFu, v, d);
        if (lane >= d) v += n;
    }
    if (lane == 31) ws[wid] = v;
    __syncthreads();
    if (wid == 0) {
        int w = ws[lane];
#pragma unroll
        for (int d = 1; d < 32; d <<= 1) {
            int n = __shfl_up_sync(0xFFFFFFFFu, w, d);
            if (lane >= d) w += n;
        }
        ws[lane] = w;
    }
    __syncthreads();
    int excl = v - s + (wid ? ws[wid - 1] : 0);

    int run = excl;
    int obase = sb * (CELLS + 1) + t * 32;
#pragma unroll
    for (int k = 0; k < 32; ++k) {
        g_offs[obase + k] = run;
        run += g_count[base + k];
    }
    if (t == 1023) g_offs[sb * (CELLS + 1) + CELLS] = run;   // = NPTS
}

// 4. scatter points into cell-sorted order, original index in .w
__global__ __launch_bounds__(256)
void k_scatter(const float* __restrict__ gts, const float* __restrict__ preds) {
    int idx = blockIdx.x * 256 + threadIdx.x;
    int sb  = idx / NPTS;
    int i   = idx - sb * NPTS;
    int side = sb >> 3, b = sb & 7;
    const float* p = (side == 0 ? gts : preds) + ((size_t)b * NPTS + i) * 3;
    float x = p[0], y = p[1], z = p[2];
    int cx, cy, cz;
    int c = cell_of(x, y, z, cx, cy, cz);
    int pos = g_offs[sb * (CELLS + 1) + c] + atomicAdd(&g_cursor[sb * CELLS + c], 1);
    g_sorted[sb * NPTS + pos] = make_float4(x, y, z, __int_as_float(i));
}

// 5. exact NN query: thread = one grid-sorted point of side A, searches the
//    grid of side B (= A^1, same batch) by expanding Chebyshev shells.
__global__ __launch_bounds__(256)
void k_query() {
    int idx  = blockIdx.x * 256 + threadIdx.x;   // 0..NTOT-1
    int qsb  = idx / NPTS;
    int slot = idx - qsb * NPTS;
    int gsb  = qsb ^ 8;                          // other side, same batch

    float4 q = g_sorted[qsb * NPTS + slot];
    int cx, cy, cz;
    cell_of(q.x, q.y, q.z, cx, cy, cz);

    const int*    offs = g_offs + gsb * (CELLS + 1);
    const float4* pts  = g_sorted + (size_t)gsb * NPTS;

    float best = FINF;
    for (int r = 0; ; ++r) {
        int zlo = max(cz - r, 0), zhi = min(cz + r, G - 1);
        for (int z = zlo; z <= zhi; ++z) {
            int adz = abs(z - cz);
            int ylo = max(cy - r, 0), yhi = min(cy + r, G - 1);
            for (int y = ylo; y <= yhi; ++y) {
                int ady  = abs(y - cy);
                int rowb = (z * G + y) * G;
                if (adz == r || ady == r) {
                    // full x range belongs to shell r
                    int xlo = max(cx - r, 0), xhi = min(cx + r, G - 1);
                    int s0 = offs[rowb + xlo];
                    int s1 = offs[rowb + xhi + 1];   // contiguous x-run
                    for (int s = s0; s < s1; ++s) {
                        float4 p = pts[s];
                        float dx = q.x - p.x, dy = q.y - p.y, dz = q.z - p.z;
                        float d2 = dx * dx + dy * dy + dz * dz;
                        best = fminf(best, d2);
                    }
                } else {
                    // interior row: only x = cx-r and cx+r are on the shell
#pragma unroll
                    for (int e = 0; e < 2; ++e) {
                        int x = (e == 0) ? cx - r : cx + r;
                        if (x < 0 || x >= G) continue;
                        int c  = rowb + x;
                        int s0 = offs[c], s1 = offs[c + 1];
                        for (int s = s0; s < s1; ++s) {
                            float4 p = pts[s];
                            float dx = q.x - p.x, dy = q.y - p.y, dz = q.z - p.z;
                            float d2 = dx * dx + dy * dy + dz * dz;
                            best = fminf(best, d2);
                        }
                    }
                }
            }
        }
        float rb = (float)r * HCELL;
        if (best <= rb * rb) break;   // all unscanned cells are >= r*h away
        if (r >= G) break;            // whole grid scanned (always has points)
    }

    int orig = __float_as_int(q.w);
    g_minbuf[qsb * NPTS + orig] = best;
}

// 6. deterministic block-tree partial sums (fixed index order)
__global__ __launch_bounds__(256)
void k_reduce() {
    __shared__ float red[256];
    int i = blockIdx.x * 256 + threadIdx.x;
    red[threadIdx.x] = g_minbuf[i];
    __syncthreads();
#pragma unroll
    for (int s = 128; s > 0; s >>= 1) {
        if (threadIdx.x < s) red[threadIdx.x] += red[threadIdx.x + s];
        __syncthreads();
    }
    if (threadIdx.x == 0) g_blocksums[blockIdx.x] = red[0];
}

// 7. final: sum 512 partials; both means share denominator BATCH*NPTS
__global__ void k_final(float* __restrict__ out) {
    __shared__ float red[512];
    red[threadIdx.x] = g_blocksums[threadIdx.x];
    __syncthreads();
#pragma unroll
    for (int s = 256; s > 0; s >>= 1) {
        if (threadIdx.x < s) red[threadIdx.x] += red[threadIdx.x + s];
        __syncthreads();
    }
    if (threadIdx.x == 0)
        out[0] = red[0] / (float)(BATCH * NPTS);
}

extern "C" void kernel_launch(void* const* d_in, const int* in_sizes, int n_in,
                              void* d_out, int out_size) {
    const float* gts   = (const float*)d_in[0];
    const float* preds = (const float*)d_in[1];
    (void)in_sizes; (void)n_in; (void)out_size;

    k_zero<<<512, 256>>>();
    k_count<<<NTOT / 256, 256>>>(gts, preds);       // 512 blocks
    k_scan<<<NSB, 1024>>>();                        // 16 blocks
    k_scatter<<<NTOT / 256, 256>>>(gts, preds);     // 512 blocks
    k_query<<<NTOT / 256, 256>>>();                 // 512 blocks
    k_reduce<<<NTOT / 256, 256>>>();                // 512 blocks -> 512 sums
    k_final<<<1, 512>>>((float*)d_out);
}